// round 7
// baseline (speedup 1.0000x reference)
#include <cuda_runtime.h>
#include <cuda_bf16.h>
#include <cstdint>

// SpatialCNN: 4 directional scans; step: out[p] += relu(conv1d_C2C(out[p_prev]))
// x (B=64, C=128, H=36, W=100), w (C, C, KS=9), fp32, in-place in d_out.
// bf16 hi/lo split (3-MMA) with mma.sync.m16n8k16, fp32 accumulate.
// R7: deep software pipelining — B frags (L2) prefetched 2 iters ahead via a
// 3-slot register ring; A frags (ldsm) prefetched 1 iter ahead (double buffer).

#define B_ 64
#define C_ 128
#define H_ 36
#define W_ 100
#define KS_ 9
#define CH_STRIDE (H_ * W_)          // 3600
#define B_STRIDE  (C_ * H_ * W_)     // 460800

#define ROWB 272                     // smem row bytes: 128 bf16 + 16B pad
#define ROWE 136                     // row stride in bf16 elems
#define NIDX 72                      // flattened (s,cif) iterations: 9*8

// Prepacked weights: [((dir*9+s)*8 + cif)*16 + co8][lane] = uint4
// uint4 = { b0hi, b1hi, b0lo, b1lo } : mma B-fragment (k=16 ci, n=8 co)
__device__ uint4 g_wPack[4 * 9 * 8 * 16 * 32];

__device__ __forceinline__ uint32_t pk_hi(float a, float b) {
    __nv_bfloat16 ha = __float2bfloat16(a), hb = __float2bfloat16(b);
    return (uint32_t)__bfloat16_as_ushort(ha) |
           ((uint32_t)__bfloat16_as_ushort(hb) << 16);
}
__device__ __forceinline__ float bf_res(float v) {     // v - bf16(v)
    return v - __bfloat162float(__float2bfloat16(v));
}

__global__ void prepack_kernel(const float* __restrict__ wd,
                               const float* __restrict__ wu,
                               const float* __restrict__ wr,
                               const float* __restrict__ wl) {
    int idx = blockIdx.x * 256 + threadIdx.x;
    const int total = 4 * 9 * 8 * 16 * 32;
    if (idx >= total) return;
    int lane = idx & 31;
    int fr   = idx >> 5;
    int co8  = fr & 15;
    int cif  = (fr >> 4) & 7;
    int rem  = fr >> 7;              // dir*9 + s
    int s    = rem % 9;
    int dir  = rem / 9;
    const float* w = (dir == 0) ? wd : (dir == 1) ? wu : (dir == 2) ? wr : wl;

    int co = co8 * 8 + (lane >> 2);
    int ci = cif * 16 + (lane & 3) * 2;
    float v00 = w[(co * C_ + ci    ) * KS_ + s];
    float v01 = w[(co * C_ + ci + 1) * KS_ + s];
    float v10 = w[(co * C_ + ci + 8) * KS_ + s];
    float v11 = w[(co * C_ + ci + 9) * KS_ + s];

    uint4 r;
    r.x = pk_hi(v00, v01);
    r.y = pk_hi(v10, v11);
    r.z = pk_hi(bf_res(v00), bf_res(v01));
    r.w = pk_hi(bf_res(v10), bf_res(v11));
    g_wPack[idx] = r;
}

__device__ __forceinline__ void ldsm4(uint32_t a[4], uint32_t addr) {
    asm volatile("ldmatrix.sync.aligned.m8n8.x4.shared.b16 {%0,%1,%2,%3}, [%4];"
                 : "=r"(a[0]), "=r"(a[1]), "=r"(a[2]), "=r"(a[3]) : "r"(addr));
}
__device__ __forceinline__ void mma16816(float c[4], const uint32_t a[4],
                                         uint32_t b0, uint32_t b1) {
    asm volatile(
        "mma.sync.aligned.m16n8k16.row.col.f32.bf16.bf16.f32 "
        "{%0,%1,%2,%3},{%4,%5,%6,%7},{%8,%9},{%0,%1,%2,%3};"
        : "+f"(c[0]), "+f"(c[1]), "+f"(c[2]), "+f"(c[3])
        : "r"(a[0]), "r"(a[1]), "r"(a[2]), "r"(a[3]), "r"(b0), "r"(b1));
}

// A-fragment smem byte offset for flat idx (s = idx>>3, cif = idx&7).
__device__ __forceinline__ uint32_t a_off(int idx) {
    return (uint32_t)(idx >> 3) * ROWB + (uint32_t)(idx & 7) * 32;
}

// One warp's share of a step-GEMM: MF m16-frags (lines) x COF co8-frags.
// Deep pipeline: B 2-ahead (ring of 3), A 1-ahead (double buffer).
template <int MF, int COF, int L, int ES>
__device__ __forceinline__ void warp_work(
    const unsigned short* sHi, const unsigned short* sLo,
    int rowbase, int co8base, int lane, int dir,
    float* __restrict__ curBase, int line0)
{
    const uint32_t aBase = (uint32_t)(lane & 15) * ROWB + ((lane >> 4) & 1) * 16
                         + (uint32_t)rowbase * ROWB;
    const uint32_t shBase = (uint32_t)__cvta_generic_to_shared(sHi) + aBase;
    const uint32_t slBase = (uint32_t)__cvta_generic_to_shared(sLo) + aBase;

    float acc[MF][COF][4];
#pragma unroll
    for (int mf = 0; mf < MF; mf++)
#pragma unroll
        for (int f = 0; f < COF; f++)
#pragma unroll
            for (int q = 0; q < 4; q++) acc[mf][f][q] = 0.0f;

    // B pointer base for this warp: frag (idx, co8) at offset (idx*16+co8)*32.
    const uint4* __restrict__ wpb = g_wPack + (size_t)(dir * NIDX * 16) * 32 + lane;

    uint4 Bq[3][COF];
    uint32_t ah[2][MF][4], al[2][MF][4];

    // Prologue: B idx 0,1 ; A idx 0.
#pragma unroll
    for (int f = 0; f < COF; f++) {
        Bq[0][f] = wpb[(size_t)(0 * 16 + co8base + f) * 32];
        Bq[1][f] = wpb[(size_t)(1 * 16 + co8base + f) * 32];
    }
#pragma unroll
    for (int mf = 0; mf < MF; mf++) {
        ldsm4(ah[0][mf], shBase + a_off(0) + mf * (16 * ROWB));
        ldsm4(al[0][mf], slBase + a_off(0) + mf * (16 * ROWB));
    }

    // Main loop: 72 = 12 x 6 so all ring indices fold to constants.
#pragma unroll 1
    for (int o = 0; o < NIDX / 6; o++) {
#pragma unroll
        for (int u = 0; u < 6; u++) {
            const int i  = o * 6 + u;
            const int cb = i % 3;            // current B slot
            const int ca = i & 1;            // current A slot

            // Prefetch B (i+2) into ring slot (i+2)%3 (clamped at tail).
            {
                const int iB = (i + 2 < NIDX) ? i + 2 : NIDX - 1;
#pragma unroll
                for (int f = 0; f < COF; f++)
                    Bq[(cb + 2) % 3][f] = wpb[(size_t)(iB * 16 + co8base + f) * 32];
            }
            // Prefetch A (i+1) into the other buffer (clamped at tail).
            {
                const int iA = (i + 1 < NIDX) ? i + 1 : NIDX - 1;
                const uint32_t off = a_off(iA);
#pragma unroll
                for (int mf = 0; mf < MF; mf++) {
                    ldsm4(ah[ca ^ 1][mf], shBase + off + mf * (16 * ROWB));
                    ldsm4(al[ca ^ 1][mf], slBase + off + mf * (16 * ROWB));
                }
            }
            // Compute with current A/B.
#pragma unroll
            for (int mf = 0; mf < MF; mf++)
#pragma unroll
                for (int f = 0; f < COF; f++) {
                    mma16816(acc[mf][f], ah[ca][mf], Bq[cb][f].x, Bq[cb][f].y); // hi*Whi
                    mma16816(acc[mf][f], ah[ca][mf], Bq[cb][f].z, Bq[cb][f].w); // hi*Wlo
                    mma16816(acc[mf][f], al[ca][mf], Bq[cb][f].x, Bq[cb][f].y); // lo*Whi
                }
        }
    }

    // Epilogue: out[cur] += relu(acc), guarded on line < L.
    const int r0 = lane >> 2;
    const int c0 = (lane & 3) * 2;
#pragma unroll
    for (int mf = 0; mf < MF; mf++) {
        const int l0 = line0 + mf * 16 + r0;
        const int l1 = l0 + 8;
#pragma unroll
        for (int f = 0; f < COF; f++) {
            const int co = (co8base + f) * 8 + c0;
            float* pc = curBase + (size_t)co * CH_STRIDE;
            if (l0 < L) {
                float* p = pc + l0 * ES;
                p[0]         += fmaxf(acc[mf][f][0], 0.0f);
                p[CH_STRIDE] += fmaxf(acc[mf][f][1], 0.0f);
            }
            if (l1 < L) {
                float* p = pc + l1 * ES;
                p[0]         += fmaxf(acc[mf][f][2], 0.0f);
                p[CH_STRIDE] += fmaxf(acc[mf][f][3], 0.0f);
            }
        }
    }
}

// Shared staging: prev slab fp32 -> bf16 hi/lo split into [WINR][ROWE] smem.
template <int WINR, int L, int ES, int THREADS>
__device__ __forceinline__ void stage_window(
    unsigned short* sHi, unsigned short* sLo,
    const float* __restrict__ prevBase, int n0, int tid)
{
    for (int i = tid; i < C_ * WINR; i += THREADS) {
        int ci = i / WINR, j = i - ci * WINR;
        int line = n0 - 4 + j;
        float v = 0.0f;
        if (line >= 0 && line < L)
            v = prevBase[ci * CH_STRIDE + line * ES];
        __nv_bfloat16 h = __float2bfloat16(v);
        float r = v - __bfloat162float(h);
        sHi[j * ROWE + ci] = __bfloat16_as_ushort(h);
        sLo[j * ROWE + ci] = __bfloat16_as_ushort(__float2bfloat16(r));
    }
}

// H-step: 512 thr = 16 warps (4 line-groups x 4 co-groups). MF=1, COF=4.
#define WINR_H 72
#define SMEM_H (2 * WINR_H * ROWB)
__global__ void __launch_bounds__(512, 1)
mma_step_h(float* __restrict__ out, int dir, int prevOff, int curOff) {
    extern __shared__ unsigned short smem_u16[];
    unsigned short* sHi = smem_u16;
    unsigned short* sLo = smem_u16 + WINR_H * ROWE;

    const int tid  = threadIdx.x;
    const int lane = tid & 31;
    const int warp = tid >> 5;
    const int b    = blockIdx.y;
    const int n0   = blockIdx.x * 64;

    stage_window<WINR_H, W_, 1, 512>(sHi, sLo,
        out + (size_t)b * B_STRIDE + prevOff, n0, tid);
    __syncthreads();

    const int lg = warp >> 2;             // 0..3 : 16-line group
    const int cg = warp & 3;              // 0..3 : 4 co8 frags
    const int line0 = n0 + lg * 16;
    if (line0 >= W_) return;              // dead tail group (tile 1)

    warp_work<1, 4, W_, 1>(sHi, sLo, lg * 16, cg * 4, lane, dir,
                           out + (size_t)b * B_STRIDE + curOff, line0);
}

// W-step: 256 thr = 8 warps (2 line-groups x 4 co-groups), co-half per blockIdx.x.
#define WINR_W 56
#define SMEM_W (2 * WINR_W * ROWB)
__global__ void __launch_bounds__(256, 1)
mma_step_w(float* __restrict__ out, int dir, int prevOff, int curOff) {
    extern __shared__ unsigned short smem_u16[];
    unsigned short* sHi = smem_u16;
    unsigned short* sLo = smem_u16 + WINR_W * ROWE;

    const int tid  = threadIdx.x;
    const int lane = tid & 31;
    const int warp = tid >> 5;
    const int b    = blockIdx.y;

    stage_window<WINR_W, H_, W_, 256>(sHi, sLo,
        out + (size_t)b * B_STRIDE + prevOff, 0, tid);
    __syncthreads();

    const int lg = warp >> 2;             // 0,1
    const int cg = warp & 3;
    const int co8base = blockIdx.x * 8 + cg * 2;
    float* curBase = out + (size_t)b * B_STRIDE + curOff;

    if (lg == 0)
        warp_work<2, 2, H_, W_>(sHi, sLo, 0, co8base, lane, dir, curBase, 0);
    else
        warp_work<1, 2, H_, W_>(sHi, sLo, 32, co8base, lane, dir, curBase, 32);
}

extern "C" void kernel_launch(void* const* d_in, const int* in_sizes, int n_in,
                              void* d_out, int out_size) {
    const float* x = (const float*)d_in[0];
    float* out = (float*)d_out;
    (void)in_sizes; (void)n_in; (void)out_size;

    // out = x (all scans accumulate in place)
    cudaMemcpyAsync(out, x, (size_t)B_ * C_ * H_ * W_ * sizeof(float),
                    cudaMemcpyDeviceToDevice, 0);

    // Pre-split + fragment-pack all weights (2.36MB, L2-resident)
    prepack_kernel<<<(4 * 9 * 8 * 16 * 32 + 255) / 256, 256>>>(
        (const float*)d_in[1], (const float*)d_in[2],
        (const float*)d_in[3], (const float*)d_in[4]);

    const dim3 gridH(2, B_);   // 2 line-tiles of 64 (second partial), full 128 co
    const dim3 gridW(2, B_);   // 2 co-halves, all 36 lines

    // Scan 1: down (axis H, forward), w_d (dir 0)
    for (int h = 1; h < H_; h++)
        mma_step_h<<<gridH, 512, SMEM_H>>>(out, 0, (h - 1) * W_, h * W_);

    // Scan 2: up (axis H, reverse), w_u (dir 1)
    for (int h = H_ - 2; h >= 0; h--)
        mma_step_h<<<gridH, 512, SMEM_H>>>(out, 1, (h + 1) * W_, h * W_);

    // Scan 3: right (axis W, forward), w_r (dir 2)
    for (int w = 1; w < W_; w++)
        mma_step_w<<<gridW, 256, SMEM_W>>>(out, 2, w - 1, w);

    // Scan 4: left (axis W, reverse), w_l (dir 3)
    for (int w = W_ - 2; w >= 0; w--)
        mma_step_w<<<gridW, 256, SMEM_W>>>(out, 3, w + 1, w);
}

// round 8
// speedup vs baseline: 1.0094x; 1.0094x over previous
#include <cuda_runtime.h>
#include <cuda_bf16.h>
#include <cstdint>

// SpatialCNN: 4 directional scans; step: out[p] += relu(conv1d_C2C(out[p_prev]))
// x (B=64, C=128, H=36, W=100), w (C, C, KS=9), fp32, in-place in d_out.
// bf16 hi/lo split (3-MMA) with mma.sync.m16n8k16, fp32 accumulate.
// R7: deep software pipelining — B frags (L2) prefetched 2 iters ahead via a
// 3-slot register ring; A frags (ldsm) prefetched 1 iter ahead (double buffer).

#define B_ 64
#define C_ 128
#define H_ 36
#define W_ 100
#define KS_ 9
#define CH_STRIDE (H_ * W_)          // 3600
#define B_STRIDE  (C_ * H_ * W_)     // 460800

#define ROWB 272                     // smem row bytes: 128 bf16 + 16B pad
#define ROWE 136                     // row stride in bf16 elems
#define NIDX 72                      // flattened (s,cif) iterations: 9*8

// Prepacked weights: [((dir*9+s)*8 + cif)*16 + co8][lane] = uint4
// uint4 = { b0hi, b1hi, b0lo, b1lo } : mma B-fragment (k=16 ci, n=8 co)
__device__ uint4 g_wPack[4 * 9 * 8 * 16 * 32];

__device__ __forceinline__ uint32_t pk_hi(float a, float b) {
    __nv_bfloat16 ha = __float2bfloat16(a), hb = __float2bfloat16(b);
    return (uint32_t)__bfloat16_as_ushort(ha) |
           ((uint32_t)__bfloat16_as_ushort(hb) << 16);
}
__device__ __forceinline__ float bf_res(float v) {     // v - bf16(v)
    return v - __bfloat162float(__float2bfloat16(v));
}

__global__ void prepack_kernel(const float* __restrict__ wd,
                               const float* __restrict__ wu,
                               const float* __restrict__ wr,
                               const float* __restrict__ wl) {
    int idx = blockIdx.x * 256 + threadIdx.x;
    const int total = 4 * 9 * 8 * 16 * 32;
    if (idx >= total) return;
    int lane = idx & 31;
    int fr   = idx >> 5;
    int co8  = fr & 15;
    int cif  = (fr >> 4) & 7;
    int rem  = fr >> 7;              // dir*9 + s
    int s    = rem % 9;
    int dir  = rem / 9;
    const float* w = (dir == 0) ? wd : (dir == 1) ? wu : (dir == 2) ? wr : wl;

    int co = co8 * 8 + (lane >> 2);
    int ci = cif * 16 + (lane & 3) * 2;
    float v00 = w[(co * C_ + ci    ) * KS_ + s];
    float v01 = w[(co * C_ + ci + 1) * KS_ + s];
    float v10 = w[(co * C_ + ci + 8) * KS_ + s];
    float v11 = w[(co * C_ + ci + 9) * KS_ + s];

    uint4 r;
    r.x = pk_hi(v00, v01);
    r.y = pk_hi(v10, v11);
    r.z = pk_hi(bf_res(v00), bf_res(v01));
    r.w = pk_hi(bf_res(v10), bf_res(v11));
    g_wPack[idx] = r;
}

__device__ __forceinline__ void ldsm4(uint32_t a[4], uint32_t addr) {
    asm volatile("ldmatrix.sync.aligned.m8n8.x4.shared.b16 {%0,%1,%2,%3}, [%4];"
                 : "=r"(a[0]), "=r"(a[1]), "=r"(a[2]), "=r"(a[3]) : "r"(addr));
}
__device__ __forceinline__ void mma16816(float c[4], const uint32_t a[4],
                                         uint32_t b0, uint32_t b1) {
    asm volatile(
        "mma.sync.aligned.m16n8k16.row.col.f32.bf16.bf16.f32 "
        "{%0,%1,%2,%3},{%4,%5,%6,%7},{%8,%9},{%0,%1,%2,%3};"
        : "+f"(c[0]), "+f"(c[1]), "+f"(c[2]), "+f"(c[3])
        : "r"(a[0]), "r"(a[1]), "r"(a[2]), "r"(a[3]), "r"(b0), "r"(b1));
}

// A-fragment smem byte offset for flat idx (s = idx>>3, cif = idx&7).
__device__ __forceinline__ uint32_t a_off(int idx) {
    return (uint32_t)(idx >> 3) * ROWB + (uint32_t)(idx & 7) * 32;
}

// One warp's share of a step-GEMM: MF m16-frags (lines) x COF co8-frags.
// Deep pipeline: B 2-ahead (ring of 3), A 1-ahead (double buffer).
template <int MF, int COF, int L, int ES>
__device__ __forceinline__ void warp_work(
    const unsigned short* sHi, const unsigned short* sLo,
    int rowbase, int co8base, int lane, int dir,
    float* __restrict__ curBase, int line0)
{
    const uint32_t aBase = (uint32_t)(lane & 15) * ROWB + ((lane >> 4) & 1) * 16
                         + (uint32_t)rowbase * ROWB;
    const uint32_t shBase = (uint32_t)__cvta_generic_to_shared(sHi) + aBase;
    const uint32_t slBase = (uint32_t)__cvta_generic_to_shared(sLo) + aBase;

    float acc[MF][COF][4];
#pragma unroll
    for (int mf = 0; mf < MF; mf++)
#pragma unroll
        for (int f = 0; f < COF; f++)
#pragma unroll
            for (int q = 0; q < 4; q++) acc[mf][f][q] = 0.0f;

    // B pointer base for this warp: frag (idx, co8) at offset (idx*16+co8)*32.
    const uint4* __restrict__ wpb = g_wPack + (size_t)(dir * NIDX * 16) * 32 + lane;

    uint4 Bq[3][COF];
    uint32_t ah[2][MF][4], al[2][MF][4];

    // Prologue: B idx 0,1 ; A idx 0.
#pragma unroll
    for (int f = 0; f < COF; f++) {
        Bq[0][f] = wpb[(size_t)(0 * 16 + co8base + f) * 32];
        Bq[1][f] = wpb[(size_t)(1 * 16 + co8base + f) * 32];
    }
#pragma unroll
    for (int mf = 0; mf < MF; mf++) {
        ldsm4(ah[0][mf], shBase + a_off(0) + mf * (16 * ROWB));
        ldsm4(al[0][mf], slBase + a_off(0) + mf * (16 * ROWB));
    }

    // Main loop: 72 = 12 x 6 so all ring indices fold to constants.
#pragma unroll 1
    for (int o = 0; o < NIDX / 6; o++) {
#pragma unroll
        for (int u = 0; u < 6; u++) {
            const int i  = o * 6 + u;
            const int cb = i % 3;            // current B slot
            const int ca = i & 1;            // current A slot

            // Prefetch B (i+2) into ring slot (i+2)%3 (clamped at tail).
            {
                const int iB = (i + 2 < NIDX) ? i + 2 : NIDX - 1;
#pragma unroll
                for (int f = 0; f < COF; f++)
                    Bq[(cb + 2) % 3][f] = wpb[(size_t)(iB * 16 + co8base + f) * 32];
            }
            // Prefetch A (i+1) into the other buffer (clamped at tail).
            {
                const int iA = (i + 1 < NIDX) ? i + 1 : NIDX - 1;
                const uint32_t off = a_off(iA);
#pragma unroll
                for (int mf = 0; mf < MF; mf++) {
                    ldsm4(ah[ca ^ 1][mf], shBase + off + mf * (16 * ROWB));
                    ldsm4(al[ca ^ 1][mf], slBase + off + mf * (16 * ROWB));
                }
            }
            // Compute with current A/B.
#pragma unroll
            for (int mf = 0; mf < MF; mf++)
#pragma unroll
                for (int f = 0; f < COF; f++) {
                    mma16816(acc[mf][f], ah[ca][mf], Bq[cb][f].x, Bq[cb][f].y); // hi*Whi
                    mma16816(acc[mf][f], ah[ca][mf], Bq[cb][f].z, Bq[cb][f].w); // hi*Wlo
                    mma16816(acc[mf][f], al[ca][mf], Bq[cb][f].x, Bq[cb][f].y); // lo*Whi
                }
        }
    }

    // Epilogue: out[cur] += relu(acc), guarded on line < L.
    const int r0 = lane >> 2;
    const int c0 = (lane & 3) * 2;
#pragma unroll
    for (int mf = 0; mf < MF; mf++) {
        const int l0 = line0 + mf * 16 + r0;
        const int l1 = l0 + 8;
#pragma unroll
        for (int f = 0; f < COF; f++) {
            const int co = (co8base + f) * 8 + c0;
            float* pc = curBase + (size_t)co * CH_STRIDE;
            if (l0 < L) {
                float* p = pc + l0 * ES;
                p[0]         += fmaxf(acc[mf][f][0], 0.0f);
                p[CH_STRIDE] += fmaxf(acc[mf][f][1], 0.0f);
            }
            if (l1 < L) {
                float* p = pc + l1 * ES;
                p[0]         += fmaxf(acc[mf][f][2], 0.0f);
                p[CH_STRIDE] += fmaxf(acc[mf][f][3], 0.0f);
            }
        }
    }
}

// Shared staging: prev slab fp32 -> bf16 hi/lo split into [WINR][ROWE] smem.
template <int WINR, int L, int ES, int THREADS>
__device__ __forceinline__ void stage_window(
    unsigned short* sHi, unsigned short* sLo,
    const float* __restrict__ prevBase, int n0, int tid)
{
    for (int i = tid; i < C_ * WINR; i += THREADS) {
        int ci = i / WINR, j = i - ci * WINR;
        int line = n0 - 4 + j;
        float v = 0.0f;
        if (line >= 0 && line < L)
            v = prevBase[ci * CH_STRIDE + line * ES];
        __nv_bfloat16 h = __float2bfloat16(v);
        float r = v - __bfloat162float(h);
        sHi[j * ROWE + ci] = __bfloat16_as_ushort(h);
        sLo[j * ROWE + ci] = __bfloat16_as_ushort(__float2bfloat16(r));
    }
}

// H-step: 512 thr = 16 warps (4 line-groups x 4 co-groups). MF=1, COF=4.
#define WINR_H 72
#define SMEM_H (2 * WINR_H * ROWB)
__global__ void __launch_bounds__(512, 1)
mma_step_h(float* __restrict__ out, int dir, int prevOff, int curOff) {
    extern __shared__ unsigned short smem_u16[];
    unsigned short* sHi = smem_u16;
    unsigned short* sLo = smem_u16 + WINR_H * ROWE;

    const int tid  = threadIdx.x;
    const int lane = tid & 31;
    const int warp = tid >> 5;
    const int b    = blockIdx.y;
    const int n0   = blockIdx.x * 64;

    stage_window<WINR_H, W_, 1, 512>(sHi, sLo,
        out + (size_t)b * B_STRIDE + prevOff, n0, tid);
    __syncthreads();

    const int lg = warp >> 2;             // 0..3 : 16-line group
    const int cg = warp & 3;              // 0..3 : 4 co8 frags
    const int line0 = n0 + lg * 16;
    if (line0 >= W_) return;              // dead tail group (tile 1)

    warp_work<1, 4, W_, 1>(sHi, sLo, lg * 16, cg * 4, lane, dir,
                           out + (size_t)b * B_STRIDE + curOff, line0);
}

// W-step: 256 thr = 8 warps (2 line-groups x 4 co-groups), co-half per blockIdx.x.
#define WINR_W 56
#define SMEM_W (2 * WINR_W * ROWB)
__global__ void __launch_bounds__(256, 1)
mma_step_w(float* __restrict__ out, int dir, int prevOff, int curOff) {
    extern __shared__ unsigned short smem_u16[];
    unsigned short* sHi = smem_u16;
    unsigned short* sLo = smem_u16 + WINR_W * ROWE;

    const int tid  = threadIdx.x;
    const int lane = tid & 31;
    const int warp = tid >> 5;
    const int b    = blockIdx.y;

    stage_window<WINR_W, H_, W_, 256>(sHi, sLo,
        out + (size_t)b * B_STRIDE + prevOff, 0, tid);
    __syncthreads();

    const int lg = warp >> 2;             // 0,1
    const int cg = warp & 3;
    const int co8base = blockIdx.x * 8 + cg * 2;
    float* curBase = out + (size_t)b * B_STRIDE + curOff;

    if (lg == 0)
        warp_work<2, 2, H_, W_>(sHi, sLo, 0, co8base, lane, dir, curBase, 0);
    else
        warp_work<1, 2, H_, W_>(sHi, sLo, 32, co8base, lane, dir, curBase, 32);
}

extern "C" void kernel_launch(void* const* d_in, const int* in_sizes, int n_in,
                              void* d_out, int out_size) {
    const float* x = (const float*)d_in[0];
    float* out = (float*)d_out;
    (void)in_sizes; (void)n_in; (void)out_size;

    // out = x (all scans accumulate in place)
    cudaMemcpyAsync(out, x, (size_t)B_ * C_ * H_ * W_ * sizeof(float),
                    cudaMemcpyDeviceToDevice, 0);

    // Pre-split + fragment-pack all weights (2.36MB, L2-resident)
    prepack_kernel<<<(4 * 9 * 8 * 16 * 32 + 255) / 256, 256>>>(
        (const float*)d_in[1], (const float*)d_in[2],
        (const float*)d_in[3], (const float*)d_in[4]);

    const dim3 gridH(2, B_);   // 2 line-tiles of 64 (second partial), full 128 co
    const dim3 gridW(2, B_);   // 2 co-halves, all 36 lines

    // Scan 1: down (axis H, forward), w_d (dir 0)
    for (int h = 1; h < H_; h++)
        mma_step_h<<<gridH, 512, SMEM_H>>>(out, 0, (h - 1) * W_, h * W_);

    // Scan 2: up (axis H, reverse), w_u (dir 1)
    for (int h = H_ - 2; h >= 0; h--)
        mma_step_h<<<gridH, 512, SMEM_H>>>(out, 1, (h + 1) * W_, h * W_);

    // Scan 3: right (axis W, forward), w_r (dir 2)
    for (int w = 1; w < W_; w++)
        mma_step_w<<<gridW, 256, SMEM_W>>>(out, 2, w - 1, w);

    // Scan 4: left (axis W, reverse), w_l (dir 3)
    for (int w = W_ - 2; w >= 0; w--)
        mma_step_w<<<gridW, 256, SMEM_W>>>(out, 3, w + 1, w);
}

// round 10
// speedup vs baseline: 1.3244x; 1.3121x over previous
#include <cuda_runtime.h>
#include <cuda_bf16.h>
#include <cstdint>

// SpatialCNN: 4 directional scans; step: out[p] += relu(conv1d_C2C(out[p_prev]))
// x (B=64, C=128, H=36, W=100), w (C, C, KS=9), fp32, in-place in d_out.
// bf16 hi/lo split (3-MMA) with mma.sync.m16n8k16, fp32 accumulate.
// R9: B-fragments delivered via cp.async SMEM ring (3 slots, 2 idx ahead) and
// read with LDS.128 — deep prefetch with ZERO register cost (R7's register ring
// spilled). A-fragments: 1-ahead ldsm double buffer.

#define B_ 64
#define C_ 128
#define H_ 36
#define W_ 100
#define KS_ 9
#define CH_STRIDE (H_ * W_)          // 3600
#define B_STRIDE  (C_ * H_ * W_)     // 460800

#define ROWB 272                     // smem A row bytes: 128 bf16 + 16B pad
#define ROWE 136                     // row stride in bf16 elems
#define NIDX 72                      // flattened (s,cif): 9*8
#define BSLAB 8192                   // bytes per idx B slab: 16 co8-frags x 512B

// Prepacked weights: [((dir*9+s)*8 + cif)*16 + co8][lane] = uint4
// uint4 = { b0hi, b1hi, b0lo, b1lo } : mma B-fragment (k=16 ci, n=8 co)
// One idx's 16 frags are 8KB contiguous -> cp.async slab copy is linear.
__device__ uint4 g_wPack[4 * NIDX * 16 * 32];

__device__ __forceinline__ uint32_t pk_hi(float a, float b) {
    __nv_bfloat16 ha = __float2bfloat16(a), hb = __float2bfloat16(b);
    return (uint32_t)__bfloat16_as_ushort(ha) |
           ((uint32_t)__bfloat16_as_ushort(hb) << 16);
}
__device__ __forceinline__ float bf_res(float v) {     // v - bf16(v)
    return v - __bfloat162float(__float2bfloat16(v));
}

__global__ void prepack_kernel(const float* __restrict__ wd,
                               const float* __restrict__ wu,
                               const float* __restrict__ wr,
                               const float* __restrict__ wl) {
    int idx = blockIdx.x * 256 + threadIdx.x;
    const int total = 4 * NIDX * 16 * 32;
    if (idx >= total) return;
    int lane = idx & 31;
    int fr   = idx >> 5;
    int co8  = fr & 15;
    int cif  = (fr >> 4) & 7;
    int rem  = fr >> 7;              // dir*9 + s
    int s    = rem % 9;
    int dir  = rem / 9;
    const float* w = (dir == 0) ? wd : (dir == 1) ? wu : (dir == 2) ? wr : wl;

    int co = co8 * 8 + (lane >> 2);
    int ci = cif * 16 + (lane & 3) * 2;
    float v00 = w[(co * C_ + ci    ) * KS_ + s];
    float v01 = w[(co * C_ + ci + 1) * KS_ + s];
    float v10 = w[(co * C_ + ci + 8) * KS_ + s];
    float v11 = w[(co * C_ + ci + 9) * KS_ + s];

    uint4 r;
    r.x = pk_hi(v00, v01);
    r.y = pk_hi(v10, v11);
    r.z = pk_hi(bf_res(v00), bf_res(v01));
    r.w = pk_hi(bf_res(v10), bf_res(v11));
    g_wPack[idx] = r;
}

__device__ __forceinline__ void ldsm4(uint32_t a[4], uint32_t addr) {
    asm volatile("ldmatrix.sync.aligned.m8n8.x4.shared.b16 {%0,%1,%2,%3}, [%4];"
                 : "=r"(a[0]), "=r"(a[1]), "=r"(a[2]), "=r"(a[3]) : "r"(addr));
}
__device__ __forceinline__ void mma16816(float c[4], const uint32_t a[4],
                                         uint32_t b0, uint32_t b1) {
    asm volatile(
        "mma.sync.aligned.m16n8k16.row.col.f32.bf16.bf16.f32 "
        "{%0,%1,%2,%3},{%4,%5,%6,%7},{%8,%9},{%0,%1,%2,%3};"
        : "+f"(c[0]), "+f"(c[1]), "+f"(c[2]), "+f"(c[3])
        : "r"(a[0]), "r"(a[1]), "r"(a[2]), "r"(a[3]), "r"(b0), "r"(b1));
}
__device__ __forceinline__ void cp16(uint32_t dst, const void* src) {
    asm volatile("cp.async.cg.shared.global [%0], [%1], 16;" :: "r"(dst), "l"(src));
}
#define CP_COMMIT() asm volatile("cp.async.commit_group;" ::: "memory")
#define CP_WAIT1()  asm volatile("cp.async.wait_group 1;" ::: "memory")

__device__ __forceinline__ uint32_t a_off(int idx) {   // s = idx>>3, cif = idx&7
    return (uint32_t)(idx >> 3) * ROWB + (uint32_t)(idx & 7) * 32;
}

// fp32 -> bf16 hi/lo split staging of the prev slab into [WINR][ROWE].
template <int WINR, int L, int ES, int THREADS>
__device__ __forceinline__ void stage_window(
    unsigned short* sHi, unsigned short* sLo,
    const float* __restrict__ prevBase, int n0, int tid)
{
    for (int i = tid; i < C_ * WINR; i += THREADS) {
        int ci = i / WINR, j = i - ci * WINR;
        int line = n0 - 4 + j;
        float v = 0.0f;
        if (line >= 0 && line < L)
            v = prevBase[ci * CH_STRIDE + line * ES];
        __nv_bfloat16 h = __float2bfloat16(v);
        float r = v - __bfloat162float(h);
        sHi[j * ROWE + ci] = __bfloat16_as_ushort(h);
        sLo[j * ROWE + ci] = __bfloat16_as_ushort(__float2bfloat16(r));
    }
}

// Core step kernel. NWARP warps = NLG line-groups x 4 co-groups, MF=1, COF co8/warp.
//   THREADS = NWARP*32, WINR = NLG*16 + 8.
// Loop over 72 idx: cp.async B(i+2) -> ring slot, barrier, LDS B(i), ldsm A(i+1),
// 3*COF MMAs with A(i)/B(i).
template <int NLG, int COF, int WINR, int L, int ES, int CO8S>
__global__ void __launch_bounds__(NLG * 4 * 32, 1)
mma_step(float* __restrict__ out, int dir, int prevOff, int curOff) {
    constexpr int THREADS = NLG * 4 * 32;
    extern __shared__ unsigned short smem_u16[];
    unsigned short* sHi = smem_u16;
    unsigned short* sLo = smem_u16 + WINR * ROWE;
    uint4* sB = (uint4*)(smem_u16 + 2 * WINR * ROWE);      // 3 slots x 512 uint4

    const int tid  = threadIdx.x;
    const int lane = tid & 31;
    const int warp = tid >> 5;
    const int b    = blockIdx.y;
    const int n0   = (CO8S == 16) ? blockIdx.x * (NLG * 16) : 0;

    const uint32_t sBb = (uint32_t)__cvta_generic_to_shared(sB);
    const char* __restrict__ wsrc =
        (const char*)g_wPack + (size_t)dir * NIDX * BSLAB;

    // Prologue: cp.async B idx 0 -> slot 0, idx 1 -> slot 1.
#pragma unroll
    for (int g = 0; g < 2; g++) {
        for (int t = tid; t < BSLAB / 16; t += THREADS)
            cp16(sBb + g * BSLAB + t * 16, wsrc + (size_t)g * BSLAB + t * 16);
        CP_COMMIT();
    }

    stage_window<WINR, L, ES, THREADS>(sHi, sLo,
        out + (size_t)b * B_STRIDE + prevOff, n0, tid);
    __syncthreads();

    const int lg = warp >> 2;                 // 0..NLG-1
    const int cg = warp & 3;
    const int co8base = (CO8S == 16) ? cg * COF : blockIdx.x * 8 + cg * COF;
    const int line0 = n0 + lg * 16;

    const uint32_t aBase = (uint32_t)(lane & 15) * ROWB + ((lane >> 4) & 1) * 16
                         + (uint32_t)(lg * 16) * ROWB;
    const uint32_t shBase = (uint32_t)__cvta_generic_to_shared(sHi) + aBase;
    const uint32_t slBase = (uint32_t)__cvta_generic_to_shared(sLo) + aBase;

    float acc[COF][4];
#pragma unroll
    for (int f = 0; f < COF; f++)
#pragma unroll
        for (int q = 0; q < 4; q++) acc[f][q] = 0.0f;

    uint32_t ah[2][4], al[2][4];
    ldsm4(ah[0], shBase + a_off(0));
    ldsm4(al[0], slBase + a_off(0));

    // 72 = 12 x 6: slot (i%3) and A-buf (i&1) fold to constants per unrolled u.
#pragma unroll 1
    for (int o = 0; o < NIDX / 6; o++) {
#pragma unroll
        for (int u = 0; u < 6; u++) {
            const int i    = o * 6 + u;
            const int slot = u % 3;           // == i % 3 (6 | period 6)
            const int ca   = u & 1;           // == i & 1

            CP_WAIT1();                       // B(i) slab resident
            __syncthreads();                  // all warps past reads of slot (i+2)%3

            // Prefetch B(i+2) into slot (i+2)%3 (clamped at tail; harmless rewrite).
            {
                const int pi = (i + 2 < NIDX) ? i + 2 : NIDX - 1;
                const int ps = (slot + 2) % 3;
                for (int t = tid; t < BSLAB / 16; t += THREADS)
                    cp16(sBb + ps * BSLAB + t * 16,
                         wsrc + (size_t)pi * BSLAB + t * 16);
                CP_COMMIT();
            }

            // B(i) from smem ring: one LDS.128 per co8-frag.
            uint4 Bq[COF];
            const uint4* __restrict__ bs = sB + slot * (BSLAB / 16) + lane;
#pragma unroll
            for (int f = 0; f < COF; f++)
                Bq[f] = bs[(co8base + f) * 32];

            // Prefetch A(i+1) into the other buffer.
            {
                const int ni = (i + 1 < NIDX) ? i + 1 : NIDX - 1;
                const uint32_t off = a_off(ni);
                ldsm4(ah[ca ^ 1], shBase + off);
                ldsm4(al[ca ^ 1], slBase + off);
            }

#pragma unroll
            for (int f = 0; f < COF; f++) {
                mma16816(acc[f], ah[ca], Bq[f].x, Bq[f].y);   // hi * Whi
                mma16816(acc[f], ah[ca], Bq[f].z, Bq[f].w);   // hi * Wlo
                mma16816(acc[f], al[ca], Bq[f].x, Bq[f].y);   // lo * Whi
            }
        }
    }

    // Epilogue: out[cur] += relu(acc), guarded on line < L.
    float* __restrict__ curBase = out + (size_t)b * B_STRIDE + curOff;
    const int r0 = lane >> 2;
    const int c0 = (lane & 3) * 2;
    const int l0 = line0 + r0;
    const int l1 = l0 + 8;
#pragma unroll
    for (int f = 0; f < COF; f++) {
        const int co = (co8base + f) * 8 + c0;
        float* pc = curBase + (size_t)co * CH_STRIDE;
        if (l0 < L) {
            float* p = pc + l0 * ES;
            p[0]         += fmaxf(acc[f][0], 0.0f);
            p[CH_STRIDE] += fmaxf(acc[f][1], 0.0f);
        }
        if (l1 < L) {
            float* p = pc + l1 * ES;
            p[0]         += fmaxf(acc[f][2], 0.0f);
            p[CH_STRIDE] += fmaxf(acc[f][3], 0.0f);
        }
    }
}

// H-step: NLG=4 (64 lines/tile), COF=4 (all 128 co), 512 thr. Grid (2, 64).
#define WINR_H 72
#define SMEM_H (2 * WINR_H * ROWE * 2 + 3 * BSLAB)    // 39168 + 24576 = 63744
// W-step: NLG=3 (48 rows, 36 valid), COF=2 (co-half per blockIdx.x), 384 thr.
#define WINR_W 56
#define SMEM_W (2 * WINR_W * ROWE * 2 + 3 * BSLAB)    // 30464 + 24576 = 55040

extern "C" void kernel_launch(void* const* d_in, const int* in_sizes, int n_in,
                              void* d_out, int out_size) {
    const float* x = (const float*)d_in[0];
    float* out = (float*)d_out;
    (void)in_sizes; (void)n_in; (void)out_size;

    cudaFuncSetAttribute((const void*)mma_step<4, 4, WINR_H, W_, 1, 16>,
                         cudaFuncAttributeMaxDynamicSharedMemorySize, SMEM_H);
    cudaFuncSetAttribute((const void*)mma_step<3, 2, WINR_W, H_, W_, 8>,
                         cudaFuncAttributeMaxDynamicSharedMemorySize, SMEM_W);

    // out = x (all scans accumulate in place)
    cudaMemcpyAsync(out, x, (size_t)B_ * C_ * H_ * W_ * sizeof(float),
                    cudaMemcpyDeviceToDevice, 0);

    // Pre-split + fragment-pack all weights (2.36MB, L2-resident)
    prepack_kernel<<<(4 * NIDX * 16 * 32 + 255) / 256, 256>>>(
        (const float*)d_in[1], (const float*)d_in[2],
        (const float*)d_in[3], (const float*)d_in[4]);

    const dim3 gridH(2, B_);   // 2 line-tiles of 64 (tile 1 partial), all 128 co
    const dim3 gridW(2, B_);   // 2 co-halves, 48-row tile (36 valid)

    // Scan 1: down (axis H, forward), w_d (dir 0)
    for (int h = 1; h < H_; h++)
        mma_step<4, 4, WINR_H, W_, 1, 16><<<gridH, 512, SMEM_H>>>(out, 0, (h - 1) * W_, h * W_);

    // Scan 2: up (axis H, reverse), w_u (dir 1)
    for (int h = H_ - 2; h >= 0; h--)
        mma_step<4, 4, WINR_H, W_, 1, 16><<<gridH, 512, SMEM_H>>>(out, 1, (h + 1) * W_, h * W_);

    // Scan 3: right (axis W, forward), w_r (dir 2)
    for (int w = 1; w < W_; w++)
        mma_step<3, 2, WINR_W, H_, W_, 8><<<gridW, 384, SMEM_W>>>(out, 2, w - 1, w);

    // Scan 4: left (axis W, reverse), w_l (dir 3)
    for (int w = W_ - 2; w >= 0; w--)
        mma_step<3, 2, WINR_W, H_, W_, 8><<<gridW, 384, SMEM_W>>>(out, 3, w + 1, w);
}

// round 11
// speedup vs baseline: 1.3299x; 1.0041x over previous
#include <cuda_runtime.h>
#include <cuda_bf16.h>
#include <cstdint>

// SpatialCNN: 4 directional scans; step: out[p] += relu(conv1d_C2C(out[p_prev]))
// bf16 hi/lo split (3-MMA) mma.sync.m16n8k16, fp32 accumulate, in-place.
// R10: B via cp.async SMEM ring of 3 thirds x 6 idx (2 groups deep, zero regs),
// ONE wait+barrier per 6 idx (R9 paid one per idx). A: 1-ahead ldsm dbl buffer.

#define B_ 64
#define C_ 128
#define H_ 36
#define W_ 100
#define KS_ 9
#define CH_STRIDE (H_ * W_)
#define B_STRIDE  (C_ * H_ * W_)

#define ROWB 272                     // smem A row bytes: 128 bf16 + 16B pad
#define ROWE 136
#define NIDX 72                      // 9 taps x 8 ci-frags
#define GSLAB 8192                   // gmem bytes per idx (16 co8-frags x 512B)

// Prepacked weights: [((dir*9+s)*8 + cif)*16 + co8][lane] = uint4
// uint4 = { b0hi, b1hi, b0lo, b1lo } : mma B-fragment (k=16 ci, n=8 co)
__device__ uint4 g_wPack[4 * NIDX * 16 * 32];

__device__ __forceinline__ uint32_t pk_hi(float a, float b) {
    __nv_bfloat16 ha = __float2bfloat16(a), hb = __float2bfloat16(b);
    return (uint32_t)__bfloat16_as_ushort(ha) |
           ((uint32_t)__bfloat16_as_ushort(hb) << 16);
}
__device__ __forceinline__ float bf_res(float v) {
    return v - __bfloat162float(__float2bfloat16(v));
}

__global__ void prepack_kernel(const float* __restrict__ wd,
                               const float* __restrict__ wu,
                               const float* __restrict__ wr,
                               const float* __restrict__ wl) {
    int idx = blockIdx.x * 256 + threadIdx.x;
    const int total = 4 * NIDX * 16 * 32;
    if (idx >= total) return;
    int lane = idx & 31;
    int fr   = idx >> 5;
    int co8  = fr & 15;
    int cif  = (fr >> 4) & 7;
    int rem  = fr >> 7;              // dir*9 + s
    int s    = rem % 9;
    int dir  = rem / 9;
    const float* w = (dir == 0) ? wd : (dir == 1) ? wu : (dir == 2) ? wr : wl;

    int co = co8 * 8 + (lane >> 2);
    int ci = cif * 16 + (lane & 3) * 2;
    float v00 = w[(co * C_ + ci    ) * KS_ + s];
    float v01 = w[(co * C_ + ci + 1) * KS_ + s];
    float v10 = w[(co * C_ + ci + 8) * KS_ + s];
    float v11 = w[(co * C_ + ci + 9) * KS_ + s];

    uint4 r;
    r.x = pk_hi(v00, v01);
    r.y = pk_hi(v10, v11);
    r.z = pk_hi(bf_res(v00), bf_res(v01));
    r.w = pk_hi(bf_res(v10), bf_res(v11));
    g_wPack[idx] = r;
}

__device__ __forceinline__ void ldsm4(uint32_t a[4], uint32_t addr) {
    asm volatile("ldmatrix.sync.aligned.m8n8.x4.shared.b16 {%0,%1,%2,%3}, [%4];"
                 : "=r"(a[0]), "=r"(a[1]), "=r"(a[2]), "=r"(a[3]) : "r"(addr));
}
__device__ __forceinline__ void mma16816(float c[4], const uint32_t a[4],
                                         uint32_t b0, uint32_t b1) {
    asm volatile(
        "mma.sync.aligned.m16n8k16.row.col.f32.bf16.bf16.f32 "
        "{%0,%1,%2,%3},{%4,%5,%6,%7},{%8,%9},{%0,%1,%2,%3};"
        : "+f"(c[0]), "+f"(c[1]), "+f"(c[2]), "+f"(c[3])
        : "r"(a[0]), "r"(a[1]), "r"(a[2]), "r"(a[3]), "r"(b0), "r"(b1));
}
__device__ __forceinline__ void cp16(uint32_t dst, const void* src) {
    asm volatile("cp.async.cg.shared.global [%0], [%1], 16;" :: "r"(dst), "l"(src));
}
#define CP_COMMIT() asm volatile("cp.async.commit_group;" ::: "memory")
#define CP_WAIT1()  asm volatile("cp.async.wait_group 1;" ::: "memory")
#define CP_WAIT0()  asm volatile("cp.async.wait_group 0;" ::: "memory")

__device__ __forceinline__ uint32_t a_off(int idx) {   // s = idx>>3, cif = idx&7
    return (uint32_t)(idx >> 3) * ROWB + (uint32_t)(idx & 7) * 32;
}

template <int WINR, int L, int ES, int THREADS>
__device__ __forceinline__ void stage_window(
    unsigned short* sHi, unsigned short* sLo,
    const float* __restrict__ prevBase, int n0, int tid)
{
    for (int i = tid; i < C_ * WINR; i += THREADS) {
        int ci = i / WINR, j = i - ci * WINR;
        int line = n0 - 4 + j;
        float v = 0.0f;
        if (line >= 0 && line < L)
            v = prevBase[ci * CH_STRIDE + line * ES];
        __nv_bfloat16 h = __float2bfloat16(v);
        float r = v - __bfloat162float(h);
        sHi[j * ROWE + ci] = __bfloat16_as_ushort(h);
        sLo[j * ROWE + ci] = __bfloat16_as_ushort(__float2bfloat16(r));
    }
}

// Step kernel. Warps = NLG line-groups x 4 co-groups; COF co8-frags per warp.
// CO8N: co8 frags held per block (16 = full co; 8 = co-half via blockIdx.x).
// B ring: 3 thirds x 6 idx x SLAB_S; one wait+barrier per 6-idx group.
template <int NLG, int COF, int WINR, int L, int ES, int CO8N>
__global__ void __launch_bounds__(NLG * 4 * 32, 1)
mma_step(float* __restrict__ out, int dir, int prevOff, int curOff) {
    constexpr int THREADS = NLG * 4 * 32;
    constexpr int SLAB_S  = CO8N * 512;           // smem bytes per idx
    constexpr int CHUNKS  = SLAB_S / 16;          // 16B chunks per idx
    extern __shared__ unsigned short smem_u16[];
    unsigned short* sHi = smem_u16;
    unsigned short* sLo = smem_u16 + WINR * ROWE;
    uint4* sB = (uint4*)(smem_u16 + 2 * WINR * ROWE);   // 18 slots

    const int tid  = threadIdx.x;
    const int lane = tid & 31;
    const int warp = tid >> 5;
    const int b    = blockIdx.y;
    const int n0   = (CO8N == 16) ? blockIdx.x * (NLG * 16) : 0;
    const uint32_t subOff = (CO8N == 16) ? 0u : blockIdx.x * (uint32_t)SLAB_S;

    const uint32_t sBb = (uint32_t)__cvta_generic_to_shared(sB);
    const char* __restrict__ wsrc =
        (const char*)g_wPack + (size_t)dir * NIDX * GSLAB + subOff;

    // Prefetch one 6-idx group into third g%3 (one cp commit group).
    auto prefetch_group = [&](int g) {
        const int third = g % 3;
        const char* src = wsrc + (size_t)(6 * g) * GSLAB;
        const uint32_t dst = sBb + (uint32_t)third * (6 * SLAB_S);
        for (int t = tid; t < 6 * CHUNKS; t += THREADS) {
            int ig = t / CHUNKS, inner = t - ig * CHUNKS;
            cp16(dst + (uint32_t)ig * SLAB_S + (uint32_t)inner * 16,
                 src + (size_t)ig * GSLAB + (size_t)inner * 16);
        }
        CP_COMMIT();
    };

    prefetch_group(0);
    prefetch_group(1);

    stage_window<WINR, L, ES, THREADS>(sHi, sLo,
        out + (size_t)b * B_STRIDE + prevOff, n0, tid);
    __syncthreads();

    const int lg = warp >> 2;
    const int cg = warp & 3;
    const int co8loc  = cg * COF;                          // index within block's slab
    const int co8glob = ((CO8N == 16) ? 0 : blockIdx.x * 8) + co8loc;
    const int line0 = n0 + lg * 16;
    const bool alive = (line0 < L);

    const uint32_t aBase = (uint32_t)(lane & 15) * ROWB + ((lane >> 4) & 1) * 16
                         + (uint32_t)(lg * 16) * ROWB;
    const uint32_t shBase = (uint32_t)__cvta_generic_to_shared(sHi) + aBase;
    const uint32_t slBase = (uint32_t)__cvta_generic_to_shared(sLo) + aBase;

    float acc[COF][4];
#pragma unroll
    for (int f = 0; f < COF; f++)
#pragma unroll
        for (int q = 0; q < 4; q++) acc[f][q] = 0.0f;

    uint32_t ah[2][4], al[2][4];
    if (alive) {
        ldsm4(ah[0], shBase + a_off(0));
        ldsm4(al[0], slBase + a_off(0));
    }

#pragma unroll 1
    for (int g = 0; g < NIDX / 6; g++) {
        if (g < NIDX / 6 - 1) CP_WAIT1();     // group g resident (g+1 may pend)
        else                  CP_WAIT0();
        __syncthreads();                       // visibility + third (g+2)%3 free
        if (g + 2 < NIDX / 6) prefetch_group(g + 2);

        if (alive) {
            const uint4* __restrict__ bt =
                sB + (size_t)(g % 3) * (6 * (SLAB_S / 16)) + lane;
#pragma unroll
            for (int u = 0; u < 6; u++) {
                const int i  = g * 6 + u;
                const int ca = u & 1;          // == i & 1 (6g even)

                // B(i) from smem: one LDS.128 per co8-frag.
                uint4 Bq[COF];
                const uint4* __restrict__ bs = bt + (size_t)u * (SLAB_S / 16);
#pragma unroll
                for (int f = 0; f < COF; f++)
                    Bq[f] = bs[(co8loc + f) * 32];

                // Prefetch A(i+1).
                const int ni = (i + 1 < NIDX) ? i + 1 : NIDX - 1;
                const uint32_t off = a_off(ni);
                ldsm4(ah[ca ^ 1], shBase + off);
                ldsm4(al[ca ^ 1], slBase + off);

#pragma unroll
                for (int f = 0; f < COF; f++) {
                    mma16816(acc[f], ah[ca], Bq[f].x, Bq[f].y);   // hi * Whi
                    mma16816(acc[f], ah[ca], Bq[f].z, Bq[f].w);   // hi * Wlo
                    mma16816(acc[f], al[ca], Bq[f].x, Bq[f].y);   // lo * Whi
                }
            }
        }
    }

    // Epilogue: out[cur] += relu(acc), guarded.
    if (alive) {
        float* __restrict__ curBase = out + (size_t)b * B_STRIDE + curOff;
        const int r0 = lane >> 2;
        const int c0 = (lane & 3) * 2;
        const int l0 = line0 + r0;
        const int l1 = l0 + 8;
#pragma unroll
        for (int f = 0; f < COF; f++) {
            const int co = (co8glob + f) * 8 + c0;
            float* pc = curBase + (size_t)co * CH_STRIDE;
            if (l0 < L) {
                float* p = pc + l0 * ES;
                p[0]         += fmaxf(acc[f][0], 0.0f);
                p[CH_STRIDE] += fmaxf(acc[f][1], 0.0f);
            }
            if (l1 < L) {
                float* p = pc + l1 * ES;
                p[0]         += fmaxf(acc[f][2], 0.0f);
                p[CH_STRIDE] += fmaxf(acc[f][3], 0.0f);
            }
        }
    }
}

// H-step: NLG=4 (64-line tiles), COF=4 (full 128 co), 512 thr, grid (2, 64).
#define WINR_H 72
#define SMEM_H (2 * WINR_H * ROWE * 2 + 18 * 16 * 512)   // 39168 + 147456 = 186624
// W-step: NLG=3 (48 rows, 36 valid), COF=2, co-half per blockIdx.x, 384 thr.
#define WINR_W 56
#define SMEM_W (2 * WINR_W * ROWE * 2 + 18 * 8 * 512)    // 30464 + 73728 = 104192

extern "C" void kernel_launch(void* const* d_in, const int* in_sizes, int n_in,
                              void* d_out, int out_size) {
    const float* x = (const float*)d_in[0];
    float* out = (float*)d_out;
    (void)in_sizes; (void)n_in; (void)out_size;

    cudaFuncSetAttribute((const void*)mma_step<4, 4, WINR_H, W_, 1, 16>,
                         cudaFuncAttributeMaxDynamicSharedMemorySize, SMEM_H);
    cudaFuncSetAttribute((const void*)mma_step<3, 2, WINR_W, H_, W_, 8>,
                         cudaFuncAttributeMaxDynamicSharedMemorySize, SMEM_W);

    // out = x (all scans accumulate in place)
    cudaMemcpyAsync(out, x, (size_t)B_ * C_ * H_ * W_ * sizeof(float),
                    cudaMemcpyDeviceToDevice, 0);

    prepack_kernel<<<(4 * NIDX * 16 * 32 + 255) / 256, 256>>>(
        (const float*)d_in[1], (const float*)d_in[2],
        (const float*)d_in[3], (const float*)d_in[4]);

    const dim3 gridH(2, B_);   // 2 line-tiles of 64 (tile 1 partial), all 128 co
    const dim3 gridW(2, B_);   // 2 co-halves, 48-row tile (36 valid)

    for (int h = 1; h < H_; h++)
        mma_step<4, 4, WINR_H, W_, 1, 16><<<gridH, 512, SMEM_H>>>(out, 0, (h - 1) * W_, h * W_);
    for (int h = H_ - 2; h >= 0; h--)
        mma_step<4, 4, WINR_H, W_, 1, 16><<<gridH, 512, SMEM_H>>>(out, 1, (h + 1) * W_, h * W_);
    for (int w = 1; w < W_; w++)
        mma_step<3, 2, WINR_W, H_, W_, 8><<<gridW, 384, SMEM_W>>>(out, 2, w - 1, w);
    for (int w = W_ - 2; w >= 0; w--)
        mma_step<3, 2, WINR_W, H_, W_, 8><<<gridW, 384, SMEM_W>>>(out, 3, w + 1, w);
}

// round 12
// speedup vs baseline: 1.8723x; 1.4079x over previous
#include <cuda_runtime.h>
#include <cuda_bf16.h>
#include <cstdint>

// SpatialCNN: 4 directional scans; step: out[p] += relu(conv1d_C2C(out[p_prev]))
// x (B=64, C=128, H=36, W=100), w (C, C, KS=9), fp32, in-place in d_out.
// bf16 hi/lo split (3-MMA) with mma.sync.m16n8k16, fp32 accumulate.
// R11 = R6 with ONE change: MMA emission reordered term-outer so consecutive
// MMAs never target the same accumulator (breaks HMMA dependent-latency chains).

#define B_ 64
#define C_ 128
#define H_ 36
#define W_ 100
#define KS_ 9
#define CH_STRIDE (H_ * W_)          // 3600
#define B_STRIDE  (C_ * H_ * W_)     // 460800

#define ROWB 272                     // smem row bytes: 128 bf16 + 16B pad
#define ROWE 136                     // row stride in bf16 elems

// Prepacked weights: [((dir*9+s)*8 + cif)*16 + co8][lane] = uint4
// uint4 = { b0hi, b1hi, b0lo, b1lo } : mma B-fragment (k=16 ci, n=8 co)
__device__ uint4 g_wPack[4 * 9 * 8 * 16 * 32];

__device__ __forceinline__ uint32_t pk_hi(float a, float b) {
    __nv_bfloat16 ha = __float2bfloat16(a), hb = __float2bfloat16(b);
    return (uint32_t)__bfloat16_as_ushort(ha) |
           ((uint32_t)__bfloat16_as_ushort(hb) << 16);
}
__device__ __forceinline__ float bf_res(float v) {     // v - bf16(v)
    return v - __bfloat162float(__float2bfloat16(v));
}

__global__ void prepack_kernel(const float* __restrict__ wd,
                               const float* __restrict__ wu,
                               const float* __restrict__ wr,
                               const float* __restrict__ wl) {
    int idx = blockIdx.x * 256 + threadIdx.x;
    const int total = 4 * 9 * 8 * 16 * 32;
    if (idx >= total) return;
    int lane = idx & 31;
    int fr   = idx >> 5;
    int co8  = fr & 15;
    int cif  = (fr >> 4) & 7;
    int rem  = fr >> 7;              // dir*9 + s
    int s    = rem % 9;
    int dir  = rem / 9;
    const float* w = (dir == 0) ? wd : (dir == 1) ? wu : (dir == 2) ? wr : wl;

    int co = co8 * 8 + (lane >> 2);
    int ci = cif * 16 + (lane & 3) * 2;
    float v00 = w[(co * C_ + ci    ) * KS_ + s];
    float v01 = w[(co * C_ + ci + 1) * KS_ + s];
    float v10 = w[(co * C_ + ci + 8) * KS_ + s];
    float v11 = w[(co * C_ + ci + 9) * KS_ + s];

    uint4 r;
    r.x = pk_hi(v00, v01);
    r.y = pk_hi(v10, v11);
    r.z = pk_hi(bf_res(v00), bf_res(v01));
    r.w = pk_hi(bf_res(v10), bf_res(v11));
    g_wPack[idx] = r;
}

__device__ __forceinline__ void ldsm4(uint32_t a[4], uint32_t addr) {
    asm volatile("ldmatrix.sync.aligned.m8n8.x4.shared.b16 {%0,%1,%2,%3}, [%4];"
                 : "=r"(a[0]), "=r"(a[1]), "=r"(a[2]), "=r"(a[3]) : "r"(addr));
}
__device__ __forceinline__ void mma16816(float c[4], const uint32_t a[4],
                                         uint32_t b0, uint32_t b1) {
    asm volatile(
        "mma.sync.aligned.m16n8k16.row.col.f32.bf16.bf16.f32 "
        "{%0,%1,%2,%3},{%4,%5,%6,%7},{%8,%9},{%0,%1,%2,%3};"
        : "+f"(c[0]), "+f"(c[1]), "+f"(c[2]), "+f"(c[3])
        : "r"(a[0]), "r"(a[1]), "r"(a[2]), "r"(a[3]), "r"(b0), "r"(b1));
}

// One warp's share of a step-GEMM: MF m16-frags (lines) x COF co8-frags.
template <int MF, int COF, int L, int ES>
__device__ __forceinline__ void warp_work(
    const unsigned short* sHi, const unsigned short* sLo,
    int rowbase, int co8base, int lane, int dir,
    float* __restrict__ curBase, int line0)
{
    const uint32_t aOff = (uint32_t)(lane & 15) * ROWB + ((lane >> 4) & 1) * 16
                        + (uint32_t)rowbase * ROWB;
    const uint32_t shBase = (uint32_t)__cvta_generic_to_shared(sHi) + aOff;
    const uint32_t slBase = (uint32_t)__cvta_generic_to_shared(sLo) + aOff;

    float acc[MF][COF][4];
#pragma unroll
    for (int mf = 0; mf < MF; mf++)
#pragma unroll
        for (int f = 0; f < COF; f++)
#pragma unroll
            for (int q = 0; q < 4; q++) acc[mf][f][q] = 0.0f;

    const uint4* __restrict__ wp = g_wPack;
    const int dbase = dir * 72;

    uint4 Bc[COF], Bn[COF];
#pragma unroll
    for (int f = 0; f < COF; f++)
        Bc[f] = wp[(dbase * 16 + co8base + f) * 32 + lane];

#pragma unroll 1
    for (int s = 0; s < 9; s++) {
#pragma unroll
        for (int cif = 0; cif < 8; cif++) {
            const int idx  = s * 8 + cif;
            const int nidx = (idx + 1 < 72) ? idx + 1 : idx;
#pragma unroll
            for (int f = 0; f < COF; f++)
                Bn[f] = wp[((dbase + nidx) * 16 + co8base + f) * 32 + lane];

            uint32_t ah[MF][4], al[MF][4];
#pragma unroll
            for (int mf = 0; mf < MF; mf++) {
                uint32_t off = (uint32_t)(s + mf * 16) * ROWB + cif * 32;
                ldsm4(ah[mf], shBase + off);
                ldsm4(al[mf], slBase + off);
            }
            // Term-outer emission: consecutive MMAs hit DIFFERENT accumulators
            // (same-acc spacing = MF*COF), breaking HMMA dependent chains.
#pragma unroll
            for (int t = 0; t < 3; t++)
#pragma unroll
                for (int mf = 0; mf < MF; mf++)
#pragma unroll
                    for (int f = 0; f < COF; f++) {
                        if (t == 0)
                            mma16816(acc[mf][f], ah[mf], Bc[f].x, Bc[f].y); // hi*Whi
                        else if (t == 1)
                            mma16816(acc[mf][f], ah[mf], Bc[f].z, Bc[f].w); // hi*Wlo
                        else
                            mma16816(acc[mf][f], al[mf], Bc[f].x, Bc[f].y); // lo*Whi
                    }
#pragma unroll
            for (int f = 0; f < COF; f++) Bc[f] = Bn[f];
        }
    }

    // Epilogue: out[cur] += relu(acc), guarded on line < L.
    const int r0 = lane >> 2;
    const int c0 = (lane & 3) * 2;
#pragma unroll
    for (int mf = 0; mf < MF; mf++) {
        const int l0 = line0 + mf * 16 + r0;
        const int l1 = l0 + 8;
#pragma unroll
        for (int f = 0; f < COF; f++) {
            const int co = (co8base + f) * 8 + c0;
            float* pc = curBase + (size_t)co * CH_STRIDE;
            if (l0 < L) {
                float* p = pc + l0 * ES;
                p[0]         += fmaxf(acc[mf][f][0], 0.0f);
                p[CH_STRIDE] += fmaxf(acc[mf][f][1], 0.0f);
            }
            if (l1 < L) {
                float* p = pc + l1 * ES;
                p[0]         += fmaxf(acc[mf][f][2], 0.0f);
                p[CH_STRIDE] += fmaxf(acc[mf][f][3], 0.0f);
            }
        }
    }
}

// Shared staging: prev slab fp32 -> bf16 hi/lo split into [WINR][ROWE] smem.
template <int WINR, int L, int ES, int THREADS>
__device__ __forceinline__ void stage_window(
    unsigned short* sHi, unsigned short* sLo,
    const float* __restrict__ prevBase, int n0, int tid)
{
    for (int i = tid; i < C_ * WINR; i += THREADS) {
        int ci = i / WINR, j = i - ci * WINR;
        int line = n0 - 4 + j;
        float v = 0.0f;
        if (line >= 0 && line < L)
            v = prevBase[ci * CH_STRIDE + line * ES];
        __nv_bfloat16 h = __float2bfloat16(v);
        float r = v - __bfloat162float(h);
        sHi[j * ROWE + ci] = __bfloat16_as_ushort(h);
        sLo[j * ROWE + ci] = __bfloat16_as_ushort(__float2bfloat16(r));
    }
}

// H-step: 512 thr = 16 warps (4 line-groups x 4 co-groups). MF=1, COF=4.
#define WINR_H 72
#define SMEM_H (2 * WINR_H * ROWB)
__global__ void __launch_bounds__(512, 1)
mma_step_h(float* __restrict__ out, int dir, int prevOff, int curOff) {
    extern __shared__ unsigned short smem_u16[];
    unsigned short* sHi = smem_u16;
    unsigned short* sLo = smem_u16 + WINR_H * ROWE;

    const int tid  = threadIdx.x;
    const int lane = tid & 31;
    const int warp = tid >> 5;
    const int b    = blockIdx.y;
    const int n0   = blockIdx.x * 64;

    stage_window<WINR_H, W_, 1, 512>(sHi, sLo,
        out + (size_t)b * B_STRIDE + prevOff, n0, tid);
    __syncthreads();

    const int lg = warp >> 2;             // 0..3 : 16-line group
    const int cg = warp & 3;              // 0..3 : 4 co8 frags
    const int line0 = n0 + lg * 16;
    if (line0 >= W_) return;              // dead tail group (tile 1)

    warp_work<1, 4, W_, 1>(sHi, sLo, lg * 16, cg * 4, lane, dir,
                           out + (size_t)b * B_STRIDE + curOff, line0);
}

// W-step: 256 thr = 8 warps (2 line-groups x 4 co-groups), co-half per blockIdx.x.
#define WINR_W 56
#define SMEM_W (2 * WINR_W * ROWB)
__global__ void __launch_bounds__(256, 1)
mma_step_w(float* __restrict__ out, int dir, int prevOff, int curOff) {
    extern __shared__ unsigned short smem_u16[];
    unsigned short* sHi = smem_u16;
    unsigned short* sLo = smem_u16 + WINR_W * ROWE;

    const int tid  = threadIdx.x;
    const int lane = tid & 31;
    const int warp = tid >> 5;
    const int b    = blockIdx.y;

    stage_window<WINR_W, H_, W_, 256>(sHi, sLo,
        out + (size_t)b * B_STRIDE + prevOff, 0, tid);
    __syncthreads();

    const int lg = warp >> 2;             // 0,1
    const int cg = warp & 3;
    const int co8base = blockIdx.x * 8 + cg * 2;
    float* curBase = out + (size_t)b * B_STRIDE + curOff;

    if (lg == 0)
        warp_work<2, 2, H_, W_>(sHi, sLo, 0, co8base, lane, dir, curBase, 0);
    else
        warp_work<1, 2, H_, W_>(sHi, sLo, 32, co8base, lane, dir, curBase, 32);
}

extern "C" void kernel_launch(void* const* d_in, const int* in_sizes, int n_in,
                              void* d_out, int out_size) {
    const float* x = (const float*)d_in[0];
    float* out = (float*)d_out;
    (void)in_sizes; (void)n_in; (void)out_size;

    // out = x (all scans accumulate in place)
    cudaMemcpyAsync(out, x, (size_t)B_ * C_ * H_ * W_ * sizeof(float),
                    cudaMemcpyDeviceToDevice, 0);

    // Pre-split + fragment-pack all weights (2.36MB, L2-resident)
    prepack_kernel<<<(4 * 9 * 8 * 16 * 32 + 255) / 256, 256>>>(
        (const float*)d_in[1], (const float*)d_in[2],
        (const float*)d_in[3], (const float*)d_in[4]);

    const dim3 gridH(2, B_);   // 2 line-tiles of 64 (second partial), full 128 co
    const dim3 gridW(2, B_);   // 2 co-halves, all 36 lines

    // Scan 1: down (axis H, forward), w_d (dir 0)
    for (int h = 1; h < H_; h++)
        mma_step_h<<<gridH, 512, SMEM_H>>>(out, 0, (h - 1) * W_, h * W_);

    // Scan 2: up (axis H, reverse), w_u (dir 1)
    for (int h = H_ - 2; h >= 0; h--)
        mma_step_h<<<gridH, 512, SMEM_H>>>(out, 1, (h + 1) * W_, h * W_);

    // Scan 3: right (axis W, forward), w_r (dir 2)
    for (int w = 1; w < W_; w++)
        mma_step_w<<<gridW, 256, SMEM_W>>>(out, 2, w - 1, w);

    // Scan 4: left (axis W, reverse), w_l (dir 3)
    for (int w = W_ - 2; w >= 0; w--)
        mma_step_w<<<gridW, 256, SMEM_W>>>(out, 3, w + 1, w);
}